// round 12
// baseline (speedup 1.0000x reference)
#include <cuda_runtime.h>
#include <math.h>

#define BB     2
#define NP     8192        // N*P
#define MM     16
#define BM     32          // BB*MM
#define CC     128
#define HH     256
#define NPAIR  (BB*NP*MM)  // 262144
#define TILE   32
#define TSTR   36          // padded row stride (floats) for sH [i][t]
#define MLP_GRID 444

typedef unsigned long long u64t;

// ---------------- scratch (device globals; no allocation) ----------------
__device__ float  g_cond[BM*HH];    // conditioning rows  (B*M, H)
__device__ int    g_count;          // inside pairs; 0 at load; reset by k_mlp arrival
__device__ int    g_done;           // k_mlp arrival counter
__device__ int    g_idx[NPAIR];     // output index of each inside pair
__device__ float4 g_xt[NPAIR];      // Xt.xyz, w = bm as int bits
__device__ __align__(16) u64t g_Wd[2*HH*HH];   // duplicated {w,w} weights [mat][i][j]

// ---------------- f32x2 packed helpers ----------------
__device__ __forceinline__ void ffma2(u64t& d, u64t h, u64t w) {
    asm("fma.rn.f32x2 %0, %1, %2, %0;" : "+l"(d) : "l"(h), "l"(w));
}
__device__ __forceinline__ u64t pack2(float a, float b) {
    u64t r;
    asm("mov.b64 %0, {%1, %2};" : "=l"(r) : "r"(__float_as_uint(a)), "r"(__float_as_uint(b)));
    return r;
}
__device__ __forceinline__ float2 unpack2(u64t v) {
    unsigned lo, hi;
    asm("mov.b64 {%0, %1}, %2;" : "=r"(lo), "=r"(hi) : "l"(v));
    return make_float2(__uint_as_float(lo), __uint_as_float(hi));
}

// ---------------- kernel 1: cond (0-31) + mask/compact (32-95) + weight dup (96-159) ----------------
__global__ void k_pre(const float* __restrict__ pts,  const float* __restrict__ trans,
                      const float* __restrict__ rot,  const float* __restrict__ scale,
                      const float* __restrict__ psf,  const float* __restrict__ Wc,
                      const float* __restrict__ bc,
                      const float* __restrict__ W1,   const float* __restrict__ W2,
                      float* __restrict__ out)
{
    int bid = blockIdx.x, tid = threadIdx.x;

    if (bid < BM) {
        __shared__ float sp[CC];
        if (tid < CC) sp[tid] = psf[bid*CC + tid];
        __syncthreads();
        float a0=0.f,a1=0.f,a2=0.f,a3=0.f,a4=0.f,a5=0.f,a6=0.f,a7=0.f;
        #pragma unroll 4
        for (int c = 0; c < CC; c += 8) {
            a0 = fmaf(sp[c+0], Wc[(c+0)*HH + tid], a0);
            a1 = fmaf(sp[c+1], Wc[(c+1)*HH + tid], a1);
            a2 = fmaf(sp[c+2], Wc[(c+2)*HH + tid], a2);
            a3 = fmaf(sp[c+3], Wc[(c+3)*HH + tid], a3);
            a4 = fmaf(sp[c+4], Wc[(c+4)*HH + tid], a4);
            a5 = fmaf(sp[c+5], Wc[(c+5)*HH + tid], a5);
            a6 = fmaf(sp[c+6], Wc[(c+6)*HH + tid], a6);
            a7 = fmaf(sp[c+7], Wc[(c+7)*HH + tid], a7);
        }
        g_cond[bid*HH + tid] = bc[tid] + ((a0+a1)+(a2+a3)) + ((a4+a5)+(a6+a7));
        return;
    }

    if (bid < BM + 64) {
        __shared__ float sR[BM*9], sT[BM*3], sS[BM*3];
        __shared__ int   sWarp[8], sBase;
        if (tid < BM) {
            float w = rot[tid*4+0], x = rot[tid*4+1], y = rot[tid*4+2], z = rot[tid*4+3];
            float n = rsqrtf(w*w + x*x + y*y + z*z);
            w *= n; x *= n; y *= n; z *= n;
            float* R = &sR[tid*9];
            R[0] = 1.f - 2.f*(y*y + z*z); R[1] = 2.f*(x*y - w*z);       R[2] = 2.f*(x*z + w*y);
            R[3] = 2.f*(x*y + w*z);       R[4] = 1.f - 2.f*(x*x + z*z); R[5] = 2.f*(y*z - w*x);
            R[6] = 2.f*(x*z - w*y);       R[7] = 2.f*(y*z + w*x);       R[8] = 1.f - 2.f*(x*x + y*y);
        }
        if (tid < BM*3) { sT[tid] = trans[tid]; sS[tid] = scale[tid]; }
        __syncthreads();

        int idx = (bid - BM) * 256 + tid;          // 0..16383
        int b   = idx >> 13;
        float px = pts[idx*3+0], py = pts[idx*3+1], pz = pts[idx*3+2];

        float4* o4 = reinterpret_cast<float4*>(out) + idx*4;
        float4 z4 = make_float4(0.f, 0.f, 0.f, 0.f);
        o4[0] = z4; o4[1] = z4; o4[2] = z4; o4[3] = z4;

        unsigned maskbits = 0;
        #pragma unroll
        for (int m = 0; m < MM; ++m) {
            int bm = b*MM + m;
            float xc = px - sT[bm*3+0], yc = py - sT[bm*3+1], zc = pz - sT[bm*3+2];
            const float* R = &sR[bm*9];
            float xt = R[0]*xc + R[1]*yc + R[2]*zc;
            float yt = R[3]*xc + R[4]*yc + R[5]*zc;
            float zt = R[6]*xc + R[7]*yc + R[8]*zc;
            float fx = xt / sS[bm*3+0], fy = yt / sS[bm*3+1], fz = zt / sS[bm*3+2];
            if (fx*fx + fy*fy + fz*fz <= 1.0f) maskbits |= (1u << m);
        }

        int cnt  = __popc(maskbits);
        int lane = tid & 31, wid = tid >> 5;
        int incl = cnt;
        #pragma unroll
        for (int d = 1; d < 32; d <<= 1) {
            int v = __shfl_up_sync(0xffffffffu, incl, d);
            if (lane >= d) incl += v;
        }
        if (lane == 31) sWarp[wid] = incl;
        __syncthreads();
        if (tid == 0) {
            int s = 0;
            #pragma unroll
            for (int w = 0; w < 8; ++w) { int t = sWarp[w]; sWarp[w] = s; s += t; }
            sBase = s ? atomicAdd(&g_count, s) : 0;
        }
        __syncthreads();
        int off = sBase + sWarp[wid] + (incl - cnt);

        unsigned mb = maskbits;
        while (mb) {
            int m = __ffs(mb) - 1; mb &= mb - 1;
            int bm = b*MM + m;
            float xc = px - sT[bm*3+0], yc = py - sT[bm*3+1], zc = pz - sT[bm*3+2];
            const float* R = &sR[bm*9];
            float xt = R[0]*xc + R[1]*yc + R[2]*zc;
            float yt = R[3]*xc + R[4]*yc + R[5]*zc;
            float zt = R[6]*xc + R[7]*yc + R[8]*zc;
            g_idx[off] = idx*MM + m;
            g_xt[off]  = make_float4(xt, yt, zt, __int_as_float(bm));
            ++off;
        }
        return;
    }

    // ---- weight duplication: blocks 96..159, 8 ull per thread ----
    {
        int t = bid - 96;                       // 0..63
        int base = (t*256 + tid) * 8;           // 0..131064
        #pragma unroll
        for (int u = 0; u < 8; ++u) {
            int e   = base + u;                 // [mat][i*256+j]
            int mat = e >> 16;
            int ij  = e & 65535;
            float w = mat ? W2[ij] : W1[ij];
            g_Wd[e] = pack2(w, w);
        }
    }
}

// ---------------- GEMM step: 4 j-streams x 8 t, one i-row, dup weights ----------------
#define GSTEP(WREG, II) { \
    const ulonglong2* hp = reinterpret_cast<const ulonglong2*>(&sH[(II)*TSTR + tq8]); \
    ulonglong2 h0 = hp[0], h1 = hp[1]; \
    u64t w0_=WREG[0], w1_=WREG[1], w2_=WREG[2], w3_=WREG[3]; \
    if ((II) + 4 < HH) { \
        const u64t* wn_ = wp_ + ((II)+4)*HH; \
        WREG[0]=wn_[0]; WREG[1]=wn_[64]; WREG[2]=wn_[128]; WREG[3]=wn_[192]; \
    } \
    ffma2(acc2[0],  h0.x, w0_); ffma2(acc2[1],  h0.y, w0_); ffma2(acc2[2],  h1.x, w0_); ffma2(acc2[3],  h1.y, w0_); \
    ffma2(acc2[4],  h0.x, w1_); ffma2(acc2[5],  h0.y, w1_); ffma2(acc2[6],  h1.x, w1_); ffma2(acc2[7],  h1.y, w1_); \
    ffma2(acc2[8],  h0.x, w2_); ffma2(acc2[9],  h0.y, w2_); ffma2(acc2[10], h1.x, w2_); ffma2(acc2[11], h1.y, w2_); \
    ffma2(acc2[12], h0.x, w3_); ffma2(acc2[13], h0.y, w3_); ffma2(acc2[14], h1.x, w3_); ffma2(acc2[15], h1.y, w3_); \
}

#define LAYER_LOOP4(Wd) { \
    const u64t* wp_ = (Wd) + jb; \
    u64t wA[4], wB[4], wC[4], wD[4]; \
    { const u64t* w0 = wp_;        wA[0]=w0[0]; wA[1]=w0[64]; wA[2]=w0[128]; wA[3]=w0[192]; } \
    { const u64t* w1 = wp_ + HH;   wB[0]=w1[0]; wB[1]=w1[64]; wB[2]=w1[128]; wB[3]=w1[192]; } \
    { const u64t* w2 = wp_ + 2*HH; wC[0]=w2[0]; wC[1]=w2[64]; wC[2]=w2[128]; wC[3]=w2[192]; } \
    { const u64t* w3 = wp_ + 3*HH; wD[0]=w3[0]; wD[1]=w3[64]; wD[2]=w3[128]; wD[3]=w3[192]; } \
    for (int i = 0; i < HH; i += 4) { \
        GSTEP(wA, i)   \
        GSTEP(wB, i+1) \
        GSTEP(wC, i+2) \
        GSTEP(wD, i+3) \
    } \
}

// ---------------- kernel 2: fused MLP, 4j x 8t, dup-weight FFMA2 ----------------
__global__ void __launch_bounds__(256, 2) k_mlp(
    const float* __restrict__ Wp, const float* __restrict__ bp,
    const float* __restrict__ b1, const float* __restrict__ b2,
    const float* __restrict__ Wout, const float* __restrict__ bout,
    float* __restrict__ out)
{
    int total = g_count;
    __syncthreads();                 // all threads have read g_count
    if (threadIdx.x == 0) {
        int old = atomicAdd(&g_done, 1);
        if (old == MLP_GRID - 1) { g_count = 0; g_done = 0; }
    }

    __shared__ __align__(16) float sH[HH*TSTR];   // 36.9 KB
    __shared__ float4 sXT[TILE];
    __shared__ int    sIdx[TILE];
    __shared__ float  sRed[8*8];                  // [warp][tt]

    int tid  = threadIdx.x;
    int lane = tid & 31, wid = tid >> 5;
    int jb   = tid & 63;          // j-stream base: j = jb + q*64
    int tq8  = (tid >> 6) * 8;    // this thread's t-slice start

    float wp0 = Wp[0*HH + tid], wp1 = Wp[1*HH + tid], wp2 = Wp[2*HH + tid];
    float bpj = bp[tid];
    float bo  = bout[0];

    for (int base = blockIdx.x * TILE; base < total; base += MLP_GRID * TILE) {
        int nt = min(TILE, total - base);
        __syncthreads();
        if (tid < TILE) {
            if (tid < nt) { sXT[tid] = g_xt[base + tid]; sIdx[tid] = g_idx[base + tid]; }
            else          { sXT[tid] = make_float4(0.f,0.f,0.f,__int_as_float(0)); sIdx[tid] = -1; }
        }
        __syncthreads();

        // ---- phase 1: relu(net0) -> sH row tid (all 32 t) ----
        {
            float v[TILE];
            #pragma unroll
            for (int t = 0; t < TILE; ++t) {
                float4 xt = sXT[t];
                int bm = __float_as_int(xt.w);
                float n0 = fmaf(wp0, xt.x, fmaf(wp1, xt.y, fmaf(wp2, xt.z,
                           bpj + __ldg(&g_cond[bm*HH + tid]))));
                v[t] = fmaxf(n0, 0.f);
            }
            #pragma unroll
            for (int t = 0; t < TILE; t += 4)
                *reinterpret_cast<float4*>(&sH[tid*TSTR + t]) =
                    make_float4(v[t], v[t+1], v[t+2], v[t+3]);
        }
        __syncthreads();

        u64t acc2[16];   // [q][t-pair]

        // ---- layer 1 ----
        #pragma unroll
        for (int k = 0; k < 16; ++k) acc2[k] = 0ull;
        LAYER_LOOP4(g_Wd);
        __syncthreads();               // all reads of sH done
        #pragma unroll
        for (int q = 0; q < 4; ++q) {
            int j = jb + q*64;
            float b1j = __ldg(&b1[j]);
            float v[8];
            #pragma unroll
            for (int p = 0; p < 4; ++p) {
                float2 u = unpack2(acc2[q*4 + p]);
                v[2*p]   = fmaxf(u.x + b1j, 0.f);
                v[2*p+1] = fmaxf(u.y + b1j, 0.f);
            }
            *reinterpret_cast<float4*>(&sH[j*TSTR + tq8])     = make_float4(v[0], v[1], v[2], v[3]);
            *reinterpret_cast<float4*>(&sH[j*TSTR + tq8 + 4]) = make_float4(v[4], v[5], v[6], v[7]);
        }
        __syncthreads();

        // ---- layer 2 ----
        #pragma unroll
        for (int k = 0; k < 16; ++k) acc2[k] = 0ull;
        LAYER_LOOP4(g_Wd + HH*HH);

        // ---- final: occ partials for this thread's 8 t over its 4 j ----
        {
            float wq0[4], wq1[4], wq2[4], bq[4], b2q[4], woq[4];
            #pragma unroll
            for (int q = 0; q < 4; ++q) {
                int j = jb + q*64;
                wq0[q] = __ldg(&Wp[j]);        wq1[q] = __ldg(&Wp[HH + j]);
                wq2[q] = __ldg(&Wp[2*HH + j]); bq[q]  = __ldg(&bp[j]);
                b2q[q] = __ldg(&b2[j]);        woq[q] = __ldg(&Wout[j]);
            }
            float ps[8];
            #pragma unroll
            for (int tt = 0; tt < 8; ++tt) {
                float4 xt = sXT[tq8 + tt];
                int bm = __float_as_int(xt.w);
                float s = 0.f;
                #pragma unroll
                for (int q = 0; q < 4; ++q) {
                    float n0 = fmaf(wq0[q], xt.x, fmaf(wq1[q], xt.y, fmaf(wq2[q], xt.z,
                               bq[q] + __ldg(&g_cond[bm*HH + jb + q*64]))));
                    float2 u = unpack2(acc2[q*4 + (tt >> 1)]);
                    float dx = (tt & 1) ? u.y : u.x;
                    s = fmaf(fmaxf(n0 + dx + b2q[q], 0.f), woq[q], s);
                }
                ps[tt] = s;
            }
            #pragma unroll
            for (int tt = 0; tt < 8; ++tt) {
                float s = ps[tt];
                s += __shfl_xor_sync(0xffffffffu, s, 16);
                s += __shfl_xor_sync(0xffffffffu, s, 8);
                s += __shfl_xor_sync(0xffffffffu, s, 4);
                s += __shfl_xor_sync(0xffffffffu, s, 2);
                s += __shfl_xor_sync(0xffffffffu, s, 1);
                ps[tt] = s;
            }
            if (lane == 0) {
                #pragma unroll
                for (int tt = 0; tt < 8; ++tt) sRed[wid*8 + tt] = ps[tt];
            }
        }
        __syncthreads();
        if (tid < TILE) {
            int t = tid, wpair = (t >> 3) * 2, tt = t & 7;
            float s = sRed[wpair*8 + tt] + sRed[wpair*8 + 8 + tt] + bo;
            int oidx = sIdx[t];
            if (oidx >= 0)
                out[oidx] = 1.0f / (1.0f + expf(-10.0f * s));
        }
    }
}

// ---------------- launcher ----------------
extern "C" void kernel_launch(void* const* d_in, const int* in_sizes, int n_in,
                              void* d_out, int out_size)
{
    const float* ray   = (const float*)d_in[0];
    const float* trans = (const float*)d_in[1];
    const float* rot   = (const float*)d_in[2];
    const float* scl   = (const float*)d_in[3];
    const float* psf   = (const float*)d_in[4];
    const float* Wp    = (const float*)d_in[5];
    const float* bp    = (const float*)d_in[6];
    const float* Wc    = (const float*)d_in[7];
    const float* bc    = (const float*)d_in[8];
    const float* W1    = (const float*)d_in[9];
    const float* b1    = (const float*)d_in[10];
    const float* W2    = (const float*)d_in[11];
    const float* b2    = (const float*)d_in[12];
    const float* Wout  = (const float*)d_in[13];
    const float* bout  = (const float*)d_in[14];
    float* out = (float*)d_out;

    k_pre<<<BM + 64 + 64, 256>>>(ray, trans, rot, scl, psf, Wc, bc, W1, W2, out);
    k_mlp<<<MLP_GRID, 256>>>(Wp, bp, b1, b2, Wout, bout, out);
}

// round 15
// speedup vs baseline: 1.1943x; 1.1943x over previous
#include <cuda_runtime.h>
#include <math.h>

#define BB     2
#define NP     8192        // N*P
#define MM     16
#define BM     32          // BB*MM
#define CC     128
#define HH     256
#define NPAIR  (BB*NP*MM)  // 262144
#define TILE   32
#define TSTR   36          // padded row stride (floats) for sH [i][t]
#define MLP_GRID 444

// dynamic smem carve (bytes)
#define SH_OFF   0
#define SW_OFF   36864      // sH: 256*36*4
#define SXT_OFF  53248      // sW: 2 * 8KB
#define SIDX_OFF 53760
#define SRED_OFF 53888
#define SMEMSZ   54400

typedef unsigned long long u64t;

// ---------------- scratch (device globals; no allocation) ----------------
__device__ float  g_cond[BM*HH];    // conditioning rows  (B*M, H)
__device__ int    g_count;          // inside pairs; 0 at load; reset by k_mlp arrival
__device__ int    g_done;           // k_mlp arrival counter
__device__ int    g_idx[NPAIR];     // output index of each inside pair
__device__ float4 g_xt[NPAIR];      // Xt.xyz, w = bm as int bits

// ---------------- f32x2 packed helpers ----------------
__device__ __forceinline__ void ffma2(u64t& d, u64t h, u64t w) {
    asm("fma.rn.f32x2 %0, %1, %2, %0;" : "+l"(d) : "l"(h), "l"(w));
}
__device__ __forceinline__ u64t splat2(float w) {
    u64t r;
    asm("mov.b64 %0, {%1, %1};" : "=l"(r) : "r"(__float_as_uint(w)));
    return r;
}
__device__ __forceinline__ float2 unpack2(u64t v) {
    unsigned lo, hi;
    asm("mov.b64 {%0, %1}, %2;" : "=r"(lo), "=r"(hi) : "l"(v));
    return make_float2(__uint_as_float(lo), __uint_as_float(hi));
}

// ---------------- kernel 1: cond rows (0-31) + mask/compact (32-95) ----------------
__global__ void k_pre(const float* __restrict__ pts,  const float* __restrict__ trans,
                      const float* __restrict__ rot,  const float* __restrict__ scale,
                      const float* __restrict__ psf,  const float* __restrict__ Wc,
                      const float* __restrict__ bc,   float* __restrict__ out)
{
    int bid = blockIdx.x, tid = threadIdx.x;

    if (bid < BM) {
        __shared__ float sp[CC];
        if (tid < CC) sp[tid] = psf[bid*CC + tid];
        __syncthreads();
        float a0=0.f,a1=0.f,a2=0.f,a3=0.f,a4=0.f,a5=0.f,a6=0.f,a7=0.f;
        #pragma unroll 4
        for (int c = 0; c < CC; c += 8) {
            a0 = fmaf(sp[c+0], Wc[(c+0)*HH + tid], a0);
            a1 = fmaf(sp[c+1], Wc[(c+1)*HH + tid], a1);
            a2 = fmaf(sp[c+2], Wc[(c+2)*HH + tid], a2);
            a3 = fmaf(sp[c+3], Wc[(c+3)*HH + tid], a3);
            a4 = fmaf(sp[c+4], Wc[(c+4)*HH + tid], a4);
            a5 = fmaf(sp[c+5], Wc[(c+5)*HH + tid], a5);
            a6 = fmaf(sp[c+6], Wc[(c+6)*HH + tid], a6);
            a7 = fmaf(sp[c+7], Wc[(c+7)*HH + tid], a7);
        }
        g_cond[bid*HH + tid] = bc[tid] + ((a0+a1)+(a2+a3)) + ((a4+a5)+(a6+a7));
        return;
    }

    __shared__ float sR[BM*9], sT[BM*3], sS[BM*3];
    __shared__ int   sWarp[8], sBase;
    if (tid < BM) {
        float w = rot[tid*4+0], x = rot[tid*4+1], y = rot[tid*4+2], z = rot[tid*4+3];
        float n = rsqrtf(w*w + x*x + y*y + z*z);
        w *= n; x *= n; y *= n; z *= n;
        float* R = &sR[tid*9];
        R[0] = 1.f - 2.f*(y*y + z*z); R[1] = 2.f*(x*y - w*z);       R[2] = 2.f*(x*z + w*y);
        R[3] = 2.f*(x*y + w*z);       R[4] = 1.f - 2.f*(x*x + z*z); R[5] = 2.f*(y*z - w*x);
        R[6] = 2.f*(x*z - w*y);       R[7] = 2.f*(y*z + w*x);       R[8] = 1.f - 2.f*(x*x + y*y);
    }
    if (tid < BM*3) { sT[tid] = trans[tid]; sS[tid] = scale[tid]; }
    __syncthreads();

    int idx = (bid - BM) * 256 + tid;          // 0..16383
    int b   = idx >> 13;
    float px = pts[idx*3+0], py = pts[idx*3+1], pz = pts[idx*3+2];

    float4* o4 = reinterpret_cast<float4*>(out) + idx*4;
    float4 z4 = make_float4(0.f, 0.f, 0.f, 0.f);
    o4[0] = z4; o4[1] = z4; o4[2] = z4; o4[3] = z4;

    unsigned maskbits = 0;
    #pragma unroll
    for (int m = 0; m < MM; ++m) {
        int bm = b*MM + m;
        float xc = px - sT[bm*3+0], yc = py - sT[bm*3+1], zc = pz - sT[bm*3+2];
        const float* R = &sR[bm*9];
        float xt = R[0]*xc + R[1]*yc + R[2]*zc;
        float yt = R[3]*xc + R[4]*yc + R[5]*zc;
        float zt = R[6]*xc + R[7]*yc + R[8]*zc;
        float fx = xt / sS[bm*3+0], fy = yt / sS[bm*3+1], fz = zt / sS[bm*3+2];
        if (fx*fx + fy*fy + fz*fz <= 1.0f) maskbits |= (1u << m);
    }

    int cnt  = __popc(maskbits);
    int lane = tid & 31, wid = tid >> 5;
    int incl = cnt;
    #pragma unroll
    for (int d = 1; d < 32; d <<= 1) {
        int v = __shfl_up_sync(0xffffffffu, incl, d);
        if (lane >= d) incl += v;
    }
    if (lane == 31) sWarp[wid] = incl;
    __syncthreads();
    if (tid == 0) {
        int s = 0;
        #pragma unroll
        for (int w = 0; w < 8; ++w) { int t = sWarp[w]; sWarp[w] = s; s += t; }
        sBase = s ? atomicAdd(&g_count, s) : 0;
    }
    __syncthreads();
    int off = sBase + sWarp[wid] + (incl - cnt);

    unsigned mb = maskbits;
    while (mb) {
        int m = __ffs(mb) - 1; mb &= mb - 1;
        int bm = b*MM + m;
        float xc = px - sT[bm*3+0], yc = py - sT[bm*3+1], zc = pz - sT[bm*3+2];
        const float* R = &sR[bm*9];
        float xt = R[0]*xc + R[1]*yc + R[2]*zc;
        float yt = R[3]*xc + R[4]*yc + R[5]*zc;
        float zt = R[6]*xc + R[7]*yc + R[8]*zc;
        g_idx[off] = idx*MM + m;
        g_xt[off]  = make_float4(xt, yt, zt, __int_as_float(bm));
        ++off;
    }
}

// ---------------- GEMM step: 4 j-streams x 8 t, weights from smem ----------------
#define GSTEP(II, RR) { \
    const ulonglong2* hp = reinterpret_cast<const ulonglong2*>(&sH[(II)*TSTR + tq8]); \
    ulonglong2 h0 = hp[0], h1 = hp[1]; \
    const float* wr = sWb + (RR)*HH + jb; \
    u64t Wl; \
    Wl = splat2(wr[0]);   ffma2(acc2[0],  h0.x, Wl); ffma2(acc2[1],  h0.y, Wl); ffma2(acc2[2],  h1.x, Wl); ffma2(acc2[3],  h1.y, Wl); \
    Wl = splat2(wr[64]);  ffma2(acc2[4],  h0.x, Wl); ffma2(acc2[5],  h0.y, Wl); ffma2(acc2[6],  h1.x, Wl); ffma2(acc2[7],  h1.y, Wl); \
    Wl = splat2(wr[128]); ffma2(acc2[8],  h0.x, Wl); ffma2(acc2[9],  h0.y, Wl); ffma2(acc2[10], h1.x, Wl); ffma2(acc2[11], h1.y, Wl); \
    Wl = splat2(wr[192]); ffma2(acc2[12], h0.x, Wl); ffma2(acc2[13], h0.y, Wl); ffma2(acc2[14], h1.x, Wl); ffma2(acc2[15], h1.y, Wl); \
}

// 32 groups of 8 i-rows; double-buffered smem staging (buf0 must be pre-filled)
#define LAYER_STAGED(Wg) { \
    int cur = 0; \
    for (int grp = 0; grp < 32; ++grp) { \
        float4 wn0, wn1; \
        if (grp < 31) { \
            const float* src = (Wg) + ((grp+1)*8 + (tid>>6))*HH + ((tid&63)<<2); \
            wn0 = *reinterpret_cast<const float4*>(src); \
            wn1 = *reinterpret_cast<const float4*>(src + 4*HH); \
        } \
        const float* sWb = sW + cur*2048; \
        int i0 = grp*8; \
        GSTEP(i0+0,0) GSTEP(i0+1,1) GSTEP(i0+2,2) GSTEP(i0+3,3) \
        GSTEP(i0+4,4) GSTEP(i0+5,5) GSTEP(i0+6,6) GSTEP(i0+7,7) \
        if (grp < 31) { \
            float* dst = sW + (cur^1)*2048 + (tid>>6)*HH + ((tid&63)<<2); \
            *reinterpret_cast<float4*>(dst) = wn0; \
            *reinterpret_cast<float4*>(dst + 4*HH) = wn1; \
        } \
        __syncthreads(); \
        cur ^= 1; \
    } \
}

// fill buf0 with group 0 of (Wg): LDG half (returns regs), STS half
#define PRELOAD_LDG(Wg, a0, a1) { \
    const float* src = (Wg) + (tid>>6)*HH + ((tid&63)<<2); \
    a0 = *reinterpret_cast<const float4*>(src); \
    a1 = *reinterpret_cast<const float4*>(src + 4*HH); \
}
#define PRELOAD_STS(a0, a1) { \
    float* dst = sW + (tid>>6)*HH + ((tid&63)<<2); \
    *reinterpret_cast<float4*>(dst) = a0; \
    *reinterpret_cast<float4*>(dst + 4*HH) = a1; \
}

// ---------------- kernel 2: fused MLP, 4j x 8t, smem-staged weights ----------------
__global__ void __launch_bounds__(256, 2) k_mlp(
    const float* __restrict__ Wp, const float* __restrict__ bp,
    const float* __restrict__ W1, const float* __restrict__ b1,
    const float* __restrict__ W2, const float* __restrict__ b2,
    const float* __restrict__ Wout, const float* __restrict__ bout,
    float* __restrict__ out)
{
    extern __shared__ __align__(16) char dsm[];
    float*  sH   = reinterpret_cast<float*>(dsm + SH_OFF);
    float*  sW   = reinterpret_cast<float*>(dsm + SW_OFF);
    float4* sXT  = reinterpret_cast<float4*>(dsm + SXT_OFF);
    int*    sIdx = reinterpret_cast<int*>(dsm + SIDX_OFF);
    float*  sRed = reinterpret_cast<float*>(dsm + SRED_OFF);

    int total = g_count;
    __syncthreads();                 // all threads have read g_count
    if (threadIdx.x == 0) {
        int old = atomicAdd(&g_done, 1);
        if (old == MLP_GRID - 1) { g_count = 0; g_done = 0; }
    }

    int tid  = threadIdx.x;
    int lane = tid & 31, wid = tid >> 5;
    int jb   = tid & 63;          // j-stream base: j = jb + q*64
    int tq8  = (tid >> 6) * 8;    // this thread's t-slice start

    float wp0 = Wp[0*HH + tid], wp1 = Wp[1*HH + tid], wp2 = Wp[2*HH + tid];
    float bpj = bp[tid];
    float bo  = bout[0];

    for (int base = blockIdx.x * TILE; base < total; base += MLP_GRID * TILE) {
        int nt = min(TILE, total - base);
        __syncthreads();
        if (tid < TILE) {
            if (tid < nt) { sXT[tid] = g_xt[base + tid]; sIdx[tid] = g_idx[base + tid]; }
            else          { sXT[tid] = make_float4(0.f,0.f,0.f,__int_as_float(0)); sIdx[tid] = -1; }
        }
        __syncthreads();

        float4 p0, p1;
        PRELOAD_LDG(W1, p0, p1);     // W1 group 0 in flight during phase 1

        // ---- phase 1: relu(net0) -> sH row tid (all 32 t) ----
        {
            float v[TILE];
            #pragma unroll
            for (int t = 0; t < TILE; ++t) {
                float4 xt = sXT[t];
                int bm = __float_as_int(xt.w);
                float n0 = fmaf(wp0, xt.x, fmaf(wp1, xt.y, fmaf(wp2, xt.z,
                           bpj + __ldg(&g_cond[bm*HH + tid]))));
                v[t] = fmaxf(n0, 0.f);
            }
            #pragma unroll
            for (int t = 0; t < TILE; t += 4)
                *reinterpret_cast<float4*>(&sH[tid*TSTR + t]) =
                    make_float4(v[t], v[t+1], v[t+2], v[t+3]);
        }
        PRELOAD_STS(p0, p1);
        __syncthreads();             // sH + sW buf0 ready

        u64t acc2[16];   // [q][t-pair]

        // ---- layer 1 ----
        #pragma unroll
        for (int k = 0; k < 16; ++k) acc2[k] = 0ull;
        LAYER_STAGED(W1);
        // last group's sync: all reads of sH/sW done

        PRELOAD_LDG(W2, p0, p1);     // W2 group 0 in flight during epilogue

        #pragma unroll
        for (int q = 0; q < 4; ++q) {
            int j = jb + q*64;
            float b1j = __ldg(&b1[j]);
            float v[8];
            #pragma unroll
            for (int p = 0; p < 4; ++p) {
                float2 u = unpack2(acc2[q*4 + p]);
                v[2*p]   = fmaxf(u.x + b1j, 0.f);
                v[2*p+1] = fmaxf(u.y + b1j, 0.f);
            }
            *reinterpret_cast<float4*>(&sH[j*TSTR + tq8])     = make_float4(v[0], v[1], v[2], v[3]);
            *reinterpret_cast<float4*>(&sH[j*TSTR + tq8 + 4]) = make_float4(v[4], v[5], v[6], v[7]);
        }
        PRELOAD_STS(p0, p1);
        __syncthreads();             // sH(acts1) + sW buf0(W2) ready

        // ---- layer 2 ----
        #pragma unroll
        for (int k = 0; k < 16; ++k) acc2[k] = 0ull;
        LAYER_STAGED(W2);

        // ---- final: occ partials for this thread's 8 t over its 4 j ----
        {
            float wq0[4], wq1[4], wq2[4], bq[4], b2q[4], woq[4];
            #pragma unroll
            for (int q = 0; q < 4; ++q) {
                int j = jb + q*64;
                wq0[q] = __ldg(&Wp[j]);        wq1[q] = __ldg(&Wp[HH + j]);
                wq2[q] = __ldg(&Wp[2*HH + j]); bq[q]  = __ldg(&bp[j]);
                b2q[q] = __ldg(&b2[j]);        woq[q] = __ldg(&Wout[j]);
            }
            float ps[8];
            #pragma unroll
            for (int tt = 0; tt < 8; ++tt) {
                float4 xt = sXT[tq8 + tt];
                int bm = __float_as_int(xt.w);
                float s = 0.f;
                #pragma unroll
                for (int q = 0; q < 4; ++q) {
                    float n0 = fmaf(wq0[q], xt.x, fmaf(wq1[q], xt.y, fmaf(wq2[q], xt.z,
                               bq[q] + __ldg(&g_cond[bm*HH + jb + q*64]))));
                    float2 u = unpack2(acc2[q*4 + (tt >> 1)]);
                    float dx = (tt & 1) ? u.y : u.x;
                    s = fmaf(fmaxf(n0 + dx + b2q[q], 0.f), woq[q], s);
                }
                ps[tt] = s;
            }
            #pragma unroll
            for (int tt = 0; tt < 8; ++tt) {
                float s = ps[tt];
                s += __shfl_xor_sync(0xffffffffu, s, 16);
                s += __shfl_xor_sync(0xffffffffu, s, 8);
                s += __shfl_xor_sync(0xffffffffu, s, 4);
                s += __shfl_xor_sync(0xffffffffu, s, 2);
                s += __shfl_xor_sync(0xffffffffu, s, 1);
                ps[tt] = s;
            }
            if (lane == 0) {
                #pragma unroll
                for (int tt = 0; tt < 8; ++tt) sRed[wid*8 + tt] = ps[tt];
            }
        }
        __syncthreads();
        if (tid < TILE) {
            int t = tid, wpair = (t >> 3) * 2, tt = t & 7;
            float s = sRed[wpair*8 + tt] + sRed[wpair*8 + 8 + tt] + bo;
            int oidx = sIdx[t];
            if (oidx >= 0)
                out[oidx] = 1.0f / (1.0f + expf(-10.0f * s));
        }
    }
}

// ---------------- launcher ----------------
extern "C" void kernel_launch(void* const* d_in, const int* in_sizes, int n_in,
                              void* d_out, int out_size)
{
    const float* ray   = (const float*)d_in[0];
    const float* trans = (const float*)d_in[1];
    const float* rot   = (const float*)d_in[2];
    const float* scl   = (const float*)d_in[3];
    const float* psf   = (const float*)d_in[4];
    const float* Wp    = (const float*)d_in[5];
    const float* bp    = (const float*)d_in[6];
    const float* Wc    = (const float*)d_in[7];
    const float* bc    = (const float*)d_in[8];
    const float* W1    = (const float*)d_in[9];
    const float* b1    = (const float*)d_in[10];
    const float* W2    = (const float*)d_in[11];
    const float* b2    = (const float*)d_in[12];
    const float* Wout  = (const float*)d_in[13];
    const float* bout  = (const float*)d_in[14];
    float* out = (float*)d_out;

    static int smem_set = 0;
    if (!smem_set) {
        cudaFuncSetAttribute(k_mlp, cudaFuncAttributeMaxDynamicSharedMemorySize, SMEMSZ);
        smem_set = 1;
    }

    k_pre<<<BM + 64, 256>>>(ray, trans, rot, scl, psf, Wc, bc, out);
    k_mlp<<<MLP_GRID, 256, SMEMSZ>>>(Wp, bp, W1, b1, W2, b2, Wout, bout, out);
}